// round 2
// baseline (speedup 1.0000x reference)
#include <cuda_runtime.h>
#include <math.h>

// Brunel network forward, GB300.
// Round 2: fix CC-tiling OOB bug (1000 % 64 != 0) -> tile = 50.
// - delayed spikes as 8-batch bitmask bytes in a 16-slot ring
// - idx compressed to uint16 once per launch
// - strictly sequential-in-c fp32 accumulation per (b,n), exact products
// - no FMA contraction in the LIF update

#define NN 10000
#define CC 1000
#define BB 8
#define TT 200
#define DELAY 15
#define REFS 20
#define MROW 10240   // padded mask row (>= NN, multiple of 16)
#define CTILE 50     // 1000 = 20 * 50  (divides evenly!)

__device__ unsigned short g_idx16[NN * CC];
__device__ float         g_v[BB * NN];
__device__ int           g_ref[BB * NN];
__device__ unsigned char g_mask[16][MROW];

__global__ void prep_kernel(const int* __restrict__ idx) {
    int i = blockIdx.x * blockDim.x + threadIdx.x;
    if (i < NN * CC) g_idx16[i] = (unsigned short)idx[i];
}

__global__ void init_kernel() {
    int i = blockIdx.x * blockDim.x + threadIdx.x;
    int stride = gridDim.x * blockDim.x;
    for (int k = i; k < BB * NN; k += stride) { g_v[k] = 0.0f; g_ref[k] = 0; }
    unsigned int* m32 = (unsigned int*)g_mask;
    for (int k = i; k < 16 * MROW / 4; k += stride) m32[k] = 0u;
}

// Block: 256 threads = 32 neurons x 8 batches. Grid: ceil(NN/32) = 313 blocks.
__global__ void __launch_bounds__(256) step_kernel(
    const float* __restrict__ ext,
    const float* __restrict__ w,
    float* __restrict__ out_spk,
    float* __restrict__ out_v,
    int t, float decay)
{
    __shared__ unsigned char  s_mask[MROW];
    __shared__ unsigned short s_idx[32 * CTILE];
    __shared__ float          s_w[32 * CTILE];

    const int tid = threadIdx.x;
    const int b   = tid & 7;        // batch lane
    const int nl  = tid >> 3;       // local neuron 0..31
    const int n0  = blockIdx.x * 32;
    const int n   = n0 + nl;

    float acc = 0.0f;

    if (t >= DELAY) {
        // Stage delayed spike bitmask (one byte per neuron, bit b = batch b)
        const uint4* src = (const uint4*)g_mask[(t - DELAY) & 15];
        uint4* dst = (uint4*)s_mask;
        #pragma unroll
        for (int i = tid; i < MROW / 16; i += 256) dst[i] = src[i];
        __syncthreads();

        const unsigned int bmask = 1u << b;
        for (int c0 = 0; c0 < CC; c0 += CTILE) {
            // Stage idx/w tile: 32 neurons x CTILE synapses (rows fully in-bounds)
            for (int k = tid; k < 32 * CTILE; k += 256) {
                int rn = k / CTILE, cc2 = k % CTILE;
                int gn = n0 + rn;
                if (gn < NN) {
                    int off = gn * CC + c0 + cc2;
                    s_idx[k] = g_idx16[off];
                    s_w[k]   = w[off];
                }
            }
            __syncthreads();
            if (n < NN) {
                const unsigned short* ip = &s_idx[nl * CTILE];
                const float*          wp = &s_w[nl * CTILE];
                #pragma unroll 10
                for (int j = 0; j < CTILE; j++) {
                    unsigned int m = (unsigned int)s_mask[ip[j]];
                    if (m & bmask) acc = __fadd_rn(acc, wp[j]);
                }
            }
            __syncthreads();
        }
    }

    float spk = 0.0f;
    if (n < NN) {
        const int sid = b * NN + n;
        float v  = g_v[sid];
        int   rf = g_ref[sid];
        float ex = ext[((size_t)t * BB + b) * NN + n];

        // v_new = (v*decay + i_rec) + ext   (left-assoc, no FMA)
        float vn = __fadd_rn(__fadd_rn(__fmul_rn(v, decay), acc), ex);
        if (rf > 0) vn = 10.0f;                 // refractory clamp BEFORE spike test
        spk = (vn >= 20.0f) ? 1.0f : 0.0f;
        float vo = (spk > 0.0f) ? 10.0f : vn;
        int   rm = rf - 1; if (rm < 0) rm = 0;
        int   ro = (spk > 0.0f) ? REFS : rm;

        g_v[sid]  = vo;
        g_ref[sid] = ro;

        size_t o = ((size_t)t * BB + b) * NN + n;
        out_spk[o] = spk;
        out_v[o]   = vo;
    }

    // Build spike bitmask byte for this step (consumed at t+DELAY)
    unsigned int ball = __ballot_sync(0xFFFFFFFFu, spk > 0.0f);
    if (b == 0 && n < NN) {
        unsigned int byte = (ball >> ((nl & 3) * 8)) & 0xFFu;
        g_mask[t & 15][n] = (unsigned char)byte;
    }
}

extern "C" void kernel_launch(void* const* d_in, const int* in_sizes, int n_in,
                              void* d_out, int out_size)
{
    const float* ext = (const float*)d_in[0];   // [T,B,N] f32
    const float* w   = (const float*)d_in[1];   // [N,C] f32
    const int*   idx = (const int*)d_in[2];     // [N,C] i32

    float* out      = (float*)d_out;
    float* out_spk  = out;                        // [T,B,N]
    float* out_v    = out + (size_t)TT * BB * NN; // [T,B,N]

    float decay = (float)exp(-0.005);             // matches np.exp(-DT/TAU_M) -> f32

    prep_kernel<<<(NN * CC + 255) / 256, 256>>>(idx);
    init_kernel<<<256, 256>>>();

    for (int t = 0; t < TT; t++) {
        step_kernel<<<313, 256>>>(ext, w, out_spk, out_v, t, decay);
    }
}

// round 3
// speedup vs baseline: 4.5655x; 4.5655x over previous
#include <cuda_runtime.h>
#include <math.h>

// Brunel network forward, GB300 — round 3.
// Count-based reformulation (bit-identical to round-2 numerics) + 8-step
// windowed kernels (25 launches) + 8-batch bit-packed counting.

#define NN 10000
#define CC 1000
#define CE 800
#define CI 200
#define BB 8
#define TT 200
#define WS 8               // steps per window
#define NWIN (TT / WS)     // 25
#define REFS 20
#define TAB_I 201
#define NWARP 24           // warps (=neurons) per block
#define THREADS (NWARP * 32)
#define NBLK ((NN + NWARP - 1) / NWARP)   // 417
#define SMEM_BYTES (NN * 16)              // 160000

__device__ unsigned short      g_idx16[NN * CC];
__device__ float               g_v[BB * NN];
__device__ int                 g_ref[BB * NN];
__device__ unsigned long long  g_spk[3][NN];     // 8 spike bytes (steps) per neuron
__device__ float               g_tab2[801 * TAB_I];

__global__ void prep_kernel(const int* __restrict__ idx) {
    int i = blockIdx.x * blockDim.x + threadIdx.x;
    if (i < NN * CC) g_idx16[i] = (unsigned short)idx[i];
}

__global__ void init_kernel(const float* __restrict__ w) {
    int i = blockIdx.x * blockDim.x + threadIdx.x;
    int stride = gridDim.x * blockDim.x;
    for (int k = i; k < BB * NN; k += stride) { g_v[k] = 0.0f; g_ref[k] = 0; }
    unsigned long long* sp = &g_spk[0][0];
    for (int k = i; k < 3 * NN; k += stride) sp[k] = 0ull;
    // tab2[e][j] = exact sequential sum: e adds of w[0], then j adds of w[CE]
    if (i < 801) {
        float we = w[0];      // 0.1f
        float wi = w[CE];     // -0.5f
        float a = 0.0f;
        for (int k = 0; k < i; k++) a = __fadd_rn(a, we);
        g_tab2[i * TAB_I] = a;
        for (int j = 1; j < TAB_I; j++) {
            a = __fadd_rn(a, wi);
            g_tab2[i * TAB_I + j] = a;
        }
    }
}

// spread bit b of m (8-bit) into byte (7-b) of a u64, value 0/1
__device__ __forceinline__ unsigned long long spread8(unsigned int m) {
    return (((unsigned long long)m * 0x8040201008040201ull) >> 7)
           & 0x0101010101010101ull;
}

// accumulate 8 steps' mask bytes (bytes 1..8 of the staged 16B row)
#define ACC8(r, cnt) do { \
    cnt[0] += spread8((r.x >>  8) & 0xFFu); \
    cnt[1] += spread8((r.x >> 16) & 0xFFu); \
    cnt[2] += spread8((r.x >> 24)        ); \
    cnt[3] += spread8((r.y      ) & 0xFFu); \
    cnt[4] += spread8((r.y >>  8) & 0xFFu); \
    cnt[5] += spread8((r.y >> 16) & 0xFFu); \
    cnt[6] += spread8((r.y >> 24)        ); \
    cnt[7] += spread8((r.z      ) & 0xFFu); \
} while (0)

__global__ void __launch_bounds__(THREADS, 1) win_kernel(
    const float* __restrict__ ext,
    float* __restrict__ out_spk,
    float* __restrict__ out_v,
    int t0, int kwin, float decay)
{
    extern __shared__ unsigned char smem[];   // [NN][16] spike-byte rows

    const int tid  = threadIdx.x;
    const int lane = tid & 31;
    const int warp = tid >> 5;
    const int n    = blockIdx.x * NWARP + warp;

    // Stage: row n = [bufA(8B) | bufB(8B)] ; bufA = window k-2, bufB = k-1
    {
        const int bufA = (kwin + 1) % 3;   // (k-2) mod 3
        const int bufB = (kwin + 2) % 3;   // (k-1) mod 3
        const unsigned long long* a = g_spk[bufA];
        const unsigned long long* b = g_spk[bufB];
        ulonglong2* dst = (ulonglong2*)smem;
        for (int i = tid; i < NN; i += THREADS) {
            ulonglong2 v2; v2.x = a[i]; v2.y = b[i];
            dst[i] = v2;
        }
    }
    __syncthreads();

    // ---- Count phase: warp = one postsynaptic neuron, all 8 batches x 8 steps
    unsigned long long cntE[WS] = {0,0,0,0,0,0,0,0};
    unsigned long long cntI[WS] = {0,0,0,0,0,0,0,0};

    if (n < NN) {
        const unsigned short* row = g_idx16 + (size_t)n * CC;
        #pragma unroll 5
        for (int j = 0; j < 25; j++) {                 // exc: c = lane + 32j (800)
            unsigned int id = row[lane + 32 * j];
            uint4 r = *((const uint4*)(smem + id * 16));
            ACC8(r, cntE);
        }
        #pragma unroll 3
        for (int j = 0; j < 6; j++) {                  // inh: 192 of 200
            unsigned int id = row[CE + lane + 32 * j];
            uint4 r = *((const uint4*)(smem + id * 16));
            ACC8(r, cntI);
        }
        if (lane < 8) {                                // inh tail: c = 992..999
            unsigned int id = row[992 + lane];
            uint4 r = *((const uint4*)(smem + id * 16));
            ACC8(r, cntI);
        }
    }

    // ---- Warp reduce: 3 byte-safe levels, widen to 16-bit lanes, 2 more levels
    int ce[WS], ci[WS];
    const unsigned long long M8 = 0x00FF00FF00FF00FFull;
    const unsigned int full = 0xFFFFFFFFu;
    const int sh = ((7 - lane) >> 1) * 16;   // 16-bit lane for batch=lane (lane<8)
    #pragma unroll
    for (int s = 0; s < WS; s++) {
        unsigned long long x = cntE[s];
        x += __shfl_xor_sync(full, x, 16);
        x += __shfl_xor_sync(full, x, 8);
        x += __shfl_xor_sync(full, x, 4);
        unsigned long long lo = x & M8, hi = (x >> 8) & M8;
        lo += __shfl_xor_sync(full, lo, 2); lo += __shfl_xor_sync(full, lo, 1);
        hi += __shfl_xor_sync(full, hi, 2); hi += __shfl_xor_sync(full, hi, 1);
        ce[s] = (int)((((lane & 1) ? lo : hi) >> sh) & 0xFFFFull);

        unsigned long long y = cntI[s];
        y += __shfl_xor_sync(full, y, 16);
        y += __shfl_xor_sync(full, y, 8);
        y += __shfl_xor_sync(full, y, 4);
        unsigned long long lo2 = y & M8, hi2 = (y >> 8) & M8;
        lo2 += __shfl_xor_sync(full, lo2, 2); lo2 += __shfl_xor_sync(full, lo2, 1);
        hi2 += __shfl_xor_sync(full, hi2, 2); hi2 += __shfl_xor_sync(full, hi2, 1);
        ci[s] = (int)((((lane & 1) ? lo2 : hi2) >> sh) & 0xFFFFull);
    }

    // ---- LIF epilogue: lanes 0..7 = batches; v/ref live in registers
    const bool act = (n < NN) && (lane < 8);
    float v = 0.0f; int rf = 0;
    float acc[WS];
    if (act) {
        const int sid = lane * NN + n;
        v  = g_v[sid];
        rf = g_ref[sid];
        #pragma unroll
        for (int s = 0; s < WS; s++)
            acc[s] = g_tab2[ce[s] * TAB_I + ci[s]];   // independent prefetches
    }
    unsigned long long spk64 = 0ull;
    #pragma unroll
    for (int s = 0; s < WS; s++) {
        bool sp = false;
        if (act) {
            const size_t o = ((size_t)(t0 + s) * BB + lane) * NN + n;
            float ex = ext[o];
            float vn = __fadd_rn(__fadd_rn(__fmul_rn(v, decay), acc[s]), ex);
            if (rf > 0) vn = 10.0f;
            sp = (vn >= 20.0f);
            float vo = sp ? 10.0f : vn;
            int rm = rf - 1; if (rm < 0) rm = 0;
            rf = sp ? REFS : rm;
            v = vo;
            out_spk[o] = sp ? 1.0f : 0.0f;
            out_v[o]   = vo;
        }
        unsigned int ball = __ballot_sync(full, sp);
        spk64 |= (unsigned long long)(ball & 0xFFu) << (8 * s);
    }
    if (act) {
        const int sid = lane * NN + n;
        g_v[sid] = v; g_ref[sid] = rf;
    }
    if (n < NN && lane == 0) g_spk[kwin % 3][n] = spk64;
}

extern "C" void kernel_launch(void* const* d_in, const int* in_sizes, int n_in,
                              void* d_out, int out_size)
{
    const float* ext = (const float*)d_in[0];   // [T,B,N]
    const float* w   = (const float*)d_in[1];   // [N,C]
    const int*   idx = (const int*)d_in[2];     // [N,C]

    float* out     = (float*)d_out;
    float* out_spk = out;
    float* out_v   = out + (size_t)TT * BB * NN;

    float decay = (float)exp(-0.005);

    cudaFuncSetAttribute(win_kernel, cudaFuncAttributeMaxDynamicSharedMemorySize,
                         SMEM_BYTES);

    prep_kernel<<<(NN * CC + 255) / 256, 256>>>(idx);
    init_kernel<<<160, 256>>>(w);

    for (int k = 0; k < NWIN; k++) {
        win_kernel<<<NBLK, THREADS, SMEM_BYTES>>>(ext, out_spk, out_v,
                                                  k * WS, k, decay);
    }
}

// round 5
// speedup vs baseline: 15.5150x; 3.3983x over previous
#include <cuda_runtime.h>
#include <math.h>

// Brunel network forward, GB300 — round 4.
// Bit-sliced CSA counting: each synapse contributes one u64 mask
// (8 steps x 8 batches); vertical carry-save counters count all 64
// positions at ~7 LOP3/mask. Numerics identical to round 3 (table-exact).

#define NN 10000
#define CC 1000
#define CE 800
#define BB 8
#define TT 200
#define WS 8
#define NWIN 25
#define REFS 20
#define TAB_I 201
#define NWARP 24
#define THREADS 768
#define GRID 148
#define CHUNK 68              // ceil(10000/148)
#define SMEM_BYTES (NN * 8)   // 80000

typedef unsigned long long u64;
typedef unsigned int u32;

__device__ u32  g_excw[NN * 400];   // 2 packed u16 idx per word, lane-coalesced
__device__ u32  g_inhw[NN * 100];
__device__ float g_v[BB * NN];
__device__ int   g_ref[BB * NN];
__device__ u64   g_spk[3][NN];      // 8 spike bytes (steps) per neuron
__device__ float g_tab2[801 * TAB_I];

__global__ void prep_kernel(const int* __restrict__ idx) {
    int i = blockIdx.x * blockDim.x + threadIdx.x;
    if (i >= NN * 500) return;
    int n = i / 500, w = i % 500;
    if (w < 400) {
        int c = 2 * w;
        u32 lo = (u32)idx[n * CC + c], hi = (u32)idx[n * CC + c + 1];
        g_excw[n * 400 + w] = lo | (hi << 16);
    } else {
        int c = CE + 2 * (w - 400);
        u32 lo = (u32)idx[n * CC + c], hi = (u32)idx[n * CC + c + 1];
        g_inhw[n * 100 + (w - 400)] = lo | (hi << 16);
    }
}

__global__ void init_kernel(const float* __restrict__ w) {
    int i = blockIdx.x * blockDim.x + threadIdx.x;
    int stride = gridDim.x * blockDim.x;
    for (int k = i; k < BB * NN; k += stride) { g_v[k] = 0.0f; g_ref[k] = 0; }
    u64* sp = &g_spk[0][0];
    for (int k = i; k < 3 * NN; k += stride) sp[k] = 0ull;
    if (i < 801) {   // exact sequential sums: i adds of w[0], then j adds of w[CE]
        float we = w[0];
        float wi = w[CE];
        float a = 0.0f;
        for (int k = 0; k < i; k++) a = __fadd_rn(a, we);
        g_tab2[i * TAB_I] = a;
        for (int j = 1; j < TAB_I; j++) {
            a = __fadd_rn(a, wi);
            g_tab2[i * TAB_I + j] = a;
        }
    }
}

// CSA step: acc += a + b (bitwise per position), returns weight-2 carry
__device__ __forceinline__ u64 csa(u64& acc, u64 a, u64 b) {
    u64 u = acc ^ a;
    u64 carry = (acc & a) | (u & b);
    acc = u ^ b;
    return carry;
}

// Butterfly-sum vertical counters over the full warp.
// p has P0 valid planes on entry, P0+5 on exit.
template<int P0>
__device__ __forceinline__ void vreduce(u64* p) {
    #pragma unroll
    for (int lev = 0; lev < 5; lev++) {
        const int P = P0 + lev;
        u64 c = 0;
        #pragma unroll
        for (int i = 0; i < P0 + 5; i++) {
            if (i < P) {
                u64 q = __shfl_xor_sync(0xFFFFFFFFu, p[i], 1 << lev);
                u64 x = p[i] ^ q;
                u64 nc = (p[i] & q) | (p[i] & c) | (q & c);   // maj -> LOP3
                p[i] = x ^ c;
                c = nc;
            }
        }
        p[P] = c;
    }
}

__global__ void __launch_bounds__(THREADS, 1) win_kernel(
    const float* __restrict__ ext,
    float* __restrict__ out_spk,
    float* __restrict__ out_v,
    int t0, int kwin, float decay)
{
    extern __shared__ u64 s_mask[];   // [NN]: byte s = delayed step t0+s-15, bit b = batch

    const int tid  = threadIdx.x;
    const int lane = tid & 31;
    const int warp = tid >> 5;
    const u32 full = 0xFFFFFFFFu;

    if (kwin > 0) {
        const u64* A = g_spk[(kwin + 1) % 3];   // window k-2
        const u64* B = g_spk[(kwin + 2) % 3];   // window k-1
        for (int i = tid; i < NN; i += THREADS)
            s_mask[i] = (A[i] >> 8) | (B[i] << 56);
        __syncthreads();
    }

    const int nbeg = blockIdx.x * CHUNK;
    const int nend = (nbeg + CHUNK < NN) ? nbeg + CHUNK : NN;

    for (int n = nbeg + warp; n < nend; n += NWARP) {
        int ce_[WS], ci_[WS];

        if (kwin > 0) {
            // ---- per-lane CSA accumulation ----
            u64 e[10], f[9];
            {
                u64 v1 = 0, v2 = 0, v4 = 0, v8 = 0, v16 = 0;
                const u32* ew = g_excw + n * 400;
                #pragma unroll
                for (int jr = 0; jr < 7; jr++) {   // 13 words (26 masks) max per lane
                    int w0i = (2 * jr) * 32 + lane;
                    int w1i = (2 * jr + 1) * 32 + lane;
                    u64 m0 = 0, m1 = 0, m2 = 0, m3 = 0;
                    if (w0i < 400) { u32 w = ew[w0i]; m0 = s_mask[w & 0xFFFFu]; m1 = s_mask[w >> 16]; }
                    if (w1i < 400) { u32 w = ew[w1i]; m2 = s_mask[w & 0xFFFFu]; m3 = s_mask[w >> 16]; }
                    u64 c1 = csa(v1, m0, m1);
                    u64 c2 = csa(v1, m2, m3);
                    u64 d  = csa(v2, c1, c2);
                    u64 t  = v4 & d; v4 ^= d;
                    u64 t2 = v8 & t; v8 ^= t;
                    v16 ^= t2;
                }
                e[0] = v1; e[1] = v2; e[2] = v4; e[3] = v8; e[4] = v16;

                u64 u1 = 0, u2 = 0, u4 = 0, u8 = 0;
                const u32* iw = g_inhw + n * 100;
                #pragma unroll
                for (int jr = 0; jr < 2; jr++) {   // 4 words (8 masks) max per lane
                    int w0i = (2 * jr) * 32 + lane;
                    int w1i = (2 * jr + 1) * 32 + lane;
                    u64 m0 = 0, m1 = 0, m2 = 0, m3 = 0;
                    if (w0i < 100) { u32 w = iw[w0i]; m0 = s_mask[w & 0xFFFFu]; m1 = s_mask[w >> 16]; }
                    if (w1i < 100) { u32 w = iw[w1i]; m2 = s_mask[w & 0xFFFFu]; m3 = s_mask[w >> 16]; }
                    u64 c1 = csa(u1, m0, m1);
                    u64 c2 = csa(u1, m2, m3);
                    u64 d  = csa(u2, c1, c2);
                    u64 t  = u4 & d; u4 ^= d;
                    u8 ^= t;
                }
                f[0] = u1; f[1] = u2; f[2] = u4; f[3] = u8;
            }

            // ---- cross-lane butterfly (bitwise vertical add) ----
            vreduce<5>(e);   // -> 10 planes, counts <= 832 < 1024
            vreduce<4>(f);   // -> 9 planes,  counts <= 256 < 512

            // ---- extraction: lane extracts positions lane and lane+32 ----
            int ceA = 0, ceB = 0, ciA = 0, ciB = 0;
            #pragma unroll
            for (int i = 0; i < 10; i++) {
                ceA |= (int)((e[i] >> lane) & 1ull) << i;
                ceB |= (int)((e[i] >> (lane + 32)) & 1ull) << i;
            }
            #pragma unroll
            for (int i = 0; i < 9; i++) {
                ciA |= (int)((f[i] >> lane) & 1ull) << i;
                ciB |= (int)((f[i] >> (lane + 32)) & 1ull) << i;
            }

            // position 8s+b: s<4 from A-half (lane 8s+b), s>=4 from B-half
            const int b = lane & 7;
            #pragma unroll
            for (int s = 0; s < WS; s++) {
                int src = 8 * (s & 3) + b;
                ce_[s] = __shfl_sync(full, (s < 4) ? ceA : ceB, src);
                ci_[s] = __shfl_sync(full, (s < 4) ? ciA : ciB, src);
            }
        } else {
            #pragma unroll
            for (int s = 0; s < WS; s++) { ce_[s] = 0; ci_[s] = 0; }
        }

        // ---- LIF epilogue: lanes 0..7 = batches ----
        const bool act = (lane < 8);
        float v = 0.0f; int rf = 0;
        float acc[WS], ex[WS];
        if (act) {
            const int sid = lane * NN + n;
            v  = g_v[sid];
            rf = g_ref[sid];
            #pragma unroll
            for (int s = 0; s < WS; s++)
                acc[s] = g_tab2[ce_[s] * TAB_I + ci_[s]];
            #pragma unroll
            for (int s = 0; s < WS; s++)
                ex[s] = ext[((size_t)(t0 + s) * BB + lane) * NN + n];
        }
        u64 spk64 = 0ull;
        #pragma unroll
        for (int s = 0; s < WS; s++) {
            bool sp = false;
            if (act) {
                float vn = __fadd_rn(__fadd_rn(__fmul_rn(v, decay), acc[s]), ex[s]);
                if (rf > 0) vn = 10.0f;
                sp = (vn >= 20.0f);
                float vo = sp ? 10.0f : vn;
                int rm = rf - 1; if (rm < 0) rm = 0;
                rf = sp ? REFS : rm;
                v = vo;
                size_t o = ((size_t)(t0 + s) * BB + lane) * NN + n;
                out_spk[o] = sp ? 1.0f : 0.0f;
                out_v[o]   = vo;
            }
            u32 ball = __ballot_sync(full, sp);
            spk64 |= (u64)(ball & 0xFFu) << (8 * s);
        }
        if (act) {
            const int sid = lane * NN + n;
            g_v[sid] = v; g_ref[sid] = rf;
        }
        if (lane == 0) g_spk[kwin % 3][n] = spk64;
    }
}

extern "C" void kernel_launch(void* const* d_in, const int* in_sizes, int n_in,
                              void* d_out, int out_size)
{
    const float* ext = (const float*)d_in[0];
    const float* w   = (const float*)d_in[1];
    const int*   idx = (const int*)d_in[2];

    float* out     = (float*)d_out;
    float* out_spk = out;
    float* out_v   = out + (size_t)TT * BB * NN;

    float decay = (float)exp(-0.005);

    cudaFuncSetAttribute(win_kernel, cudaFuncAttributeMaxDynamicSharedMemorySize,
                         SMEM_BYTES);

    prep_kernel<<<(NN * 500 + 255) / 256, 256>>>(idx);
    init_kernel<<<160, 256>>>(w);

    for (int k = 0; k < NWIN; k++) {
        win_kernel<<<GRID, THREADS, SMEM_BYTES>>>(ext, out_spk, out_v,
                                                  k * WS, k, decay);
    }
}